// round 10
// baseline (speedup 1.0000x reference)
#include <cuda_runtime.h>
#include <cuda_bf16.h>
#include <cuda_fp16.h>
#include <cstdint>

#define N_NODES 50000
#define D 128
#define N_EDGES 640000
#define S_BLK 64                       // sort blocks (wave-1 resident: < 148)
#define GRID_TOT 296
#define NGB ((N_NODES + 127) / 128)    // 391 gemm tiles
#define CHUNK 4                        // scan items per sort thread
#define NT (S_BLK * 256)               // sort threads = 16384

// ---- dynamic smem layout (float2 {hi,lo} interleaved tiles) ----
// sA: 128 rows x 34 float2 (stride pad for 16B-aligned rows)  = 34816 B
// sB: 32 k x 130 float2                                       = 33280 B
#define SA_STRIDE 34
#define SB_STRIDE 130
#define SM_A 0
#define SM_B (128 * SA_STRIDE * 8)                  // 34816
#define SM_SS (SM_B + 32 * SB_STRIDE * 8)           // 68096 (sort scan, 1KB)
#define SM_TILE (SM_SS + 1024)                      // 69120 (work-steal bcast)
#define SMEM_TOTAL (SM_TILE + 8)                    // 69128 B

// 3-product tf32 mma: D += Ah*Bh + Ah*Bl + Al*Bh  (fp32-grade accuracy)
#define MMA_TF32(d, a0, a1, a2, a3, b0, b1) \
    asm volatile("mma.sync.aligned.m16n8k8.row.col.f32.tf32.tf32.f32 " \
        "{%0,%1,%2,%3}, {%4,%5,%6,%7}, {%8,%9}, {%0,%1,%2,%3};" \
        : "+f"((d)[0]), "+f"((d)[1]), "+f"((d)[2]), "+f"((d)[3]) \
        : "r"(a0), "r"(a1), "r"(a2), "r"(a3), "r"(b0), "r"(b1))

__device__ __forceinline__ float tf32_hi(float x) {
    return __int_as_float(__float_as_int(x) & 0xFFFFE000);
}

// ---- device scratch (no allocs allowed; zero-initialized) ----
__device__ __half g_Yh[(size_t)N_NODES * D];  // feat @ W in fp16 (12.8 MB)
__device__ int   g_count[N_NODES];
__device__ int   g_offset[N_NODES];
__device__ int   g_bsum[S_BLK];
__device__ int   g_bbase[S_BLK];
__device__ int   g_src_sorted[N_EDGES];
__device__ int   g_is64;
__device__ unsigned g_bar_cnt;
__device__ unsigned g_tile;
__device__ unsigned g_done;

__device__ __forceinline__ void sort_barrier(unsigned target) {
    __syncthreads();
    if (threadIdx.x == 0) {
        __threadfence();
        atomicAdd(&g_bar_cnt, 1u);
        while (*((volatile unsigned*)&g_bar_cnt) < target) __nanosleep(64);
        __threadfence();
    }
    __syncthreads();
}

// ---------------------------------------------------------------------------
// Mega kernel: blocks [0,S_BLK) run the sort chain then join the gemm pool;
// blocks [S_BLK,GRID_TOT) run tf32-split mma.sync gemm tiles immediately.
// gemm: g_Yh = fp16(feat @ W). 128x128 tile, 8 warps (4x2), warp tile 32x64.
// ---------------------------------------------------------------------------
extern "C" __global__ void __launch_bounds__(256)
mega_kernel(const float* __restrict__ feat, const float* __restrict__ W,
            const void* __restrict__ srcp, const void* __restrict__ dstp) {
    extern __shared__ char smem[];
    float2* smA = (float2*)(smem + SM_A);   // [m][k] {hi,lo}
    float2* smB = (float2*)(smem + SM_B);   // [k][n] {hi,lo}
    const int tid = threadIdx.x;

    if (blockIdx.x < S_BLK) {
        // ================= SORT CHAIN (unchanged from passing R8) ==========
        const int b = blockIdx.x;
        const int st = b * 256 + tid;
        int* ss = (int*)(smem + SM_SS);

        for (int i = st; i < N_NODES; i += NT) g_count[i] = 0;
        if (b == 0 && tid < 32) {
            // int32 read as int64 packs two indices; high half is a random
            // node index (nonzero w.p. ~1-2e-5) -> out-of-range identifies it.
            const long long* s64 = (const long long*)srcp;
            const long long* d64 = (const long long*)dstp;
            int bad = 0;
#pragma unroll
            for (int r = 0; r < 2; r++) {
                int i = tid + r * 32;
                long long a = s64[i], c = d64[i];
                bad |= (a < 0 || a >= N_NODES || c < 0 || c >= N_NODES);
            }
            unsigned m = __ballot_sync(0xFFFFFFFFu, bad);
            if (tid == 0) g_is64 = (m == 0u);
        }
        sort_barrier(1u * S_BLK);

        const int is64 = g_is64;
        {   // hist (4x batched)
            int e = st;
            if (is64) {
                const long long* dd = (const long long*)dstp;
                for (; e + 3 * NT < N_EDGES; e += 4 * NT) {
                    int d0 = (int)dd[e], d1 = (int)dd[e + NT];
                    int d2 = (int)dd[e + 2 * NT], d3 = (int)dd[e + 3 * NT];
                    atomicAdd(&g_count[d0], 1); atomicAdd(&g_count[d1], 1);
                    atomicAdd(&g_count[d2], 1); atomicAdd(&g_count[d3], 1);
                }
                for (; e < N_EDGES; e += NT) atomicAdd(&g_count[(int)dd[e]], 1);
            } else {
                const int* dd = (const int*)dstp;
                for (; e + 3 * NT < N_EDGES; e += 4 * NT) {
                    int d0 = dd[e], d1 = dd[e + NT];
                    int d2 = dd[e + 2 * NT], d3 = dd[e + 3 * NT];
                    atomicAdd(&g_count[d0], 1); atomicAdd(&g_count[d1], 1);
                    atomicAdd(&g_count[d2], 1); atomicAdd(&g_count[d3], 1);
                }
                for (; e < N_EDGES; e += NT) atomicAdd(&g_count[dd[e]], 1);
            }
        }
        sort_barrier(2u * S_BLK);

        // scan
        const int g0 = st * CHUNK;
        int csum = 0, cv[CHUNK];
#pragma unroll
        for (int i = 0; i < CHUNK; i++) {
            int g = g0 + i;
            cv[i] = (g < N_NODES) ? g_count[g] : 0;
            csum += cv[i];
        }
        ss[tid] = csum;
        __syncthreads();
#pragma unroll
        for (int off = 1; off < 256; off <<= 1) {
            int v = ss[tid];
            int u = (tid >= off) ? ss[tid - off] : 0;
            __syncthreads();
            ss[tid] = v + u;
            __syncthreads();
        }
        const int texcl = ss[tid] - csum;
        if (tid == 255) g_bsum[b] = ss[255];
        sort_barrier(3u * S_BLK);

        if (b == 0) {
            int v0 = (tid < S_BLK) ? g_bsum[tid] : 0;
            ss[tid] = v0;
            __syncthreads();
#pragma unroll
            for (int off = 1; off < S_BLK; off <<= 1) {
                int v = ss[tid];
                int u = (tid >= off) ? ss[tid - off] : 0;
                __syncthreads();
                ss[tid] = v + u;
                __syncthreads();
            }
            if (tid < S_BLK) g_bbase[tid] = ss[tid] - v0;
        }
        sort_barrier(4u * S_BLK);

        {
            int run = g_bbase[b] + texcl;
#pragma unroll
            for (int i = 0; i < CHUNK; i++) {
                int g = g0 + i;
                if (g < N_NODES) g_offset[g] = run;
                run += cv[i];
            }
        }
        sort_barrier(5u * S_BLK);

        {   // scatter (4x batched)
            int e = st;
            if (is64) {
                const long long* dd = (const long long*)dstp;
                const long long* sv = (const long long*)srcp;
                for (; e + 3 * NT < N_EDGES; e += 4 * NT) {
                    int d0 = (int)dd[e],          s0 = (int)sv[e];
                    int d1 = (int)dd[e + NT],     s1 = (int)sv[e + NT];
                    int d2 = (int)dd[e + 2 * NT], s2 = (int)sv[e + 2 * NT];
                    int d3 = (int)dd[e + 3 * NT], s3 = (int)sv[e + 3 * NT];
                    int p0 = atomicAdd(&g_offset[d0], 1);
                    int p1 = atomicAdd(&g_offset[d1], 1);
                    int p2 = atomicAdd(&g_offset[d2], 1);
                    int p3 = atomicAdd(&g_offset[d3], 1);
                    g_src_sorted[p0] = s0; g_src_sorted[p1] = s1;
                    g_src_sorted[p2] = s2; g_src_sorted[p3] = s3;
                }
                for (; e < N_EDGES; e += NT)
                    g_src_sorted[atomicAdd(&g_offset[(int)dd[e]], 1)] = (int)sv[e];
            } else {
                const int* dd = (const int*)dstp;
                const int* sv = (const int*)srcp;
                for (; e + 3 * NT < N_EDGES; e += 4 * NT) {
                    int d0 = dd[e],          s0 = sv[e];
                    int d1 = dd[e + NT],     s1 = sv[e + NT];
                    int d2 = dd[e + 2 * NT], s2 = sv[e + 2 * NT];
                    int d3 = dd[e + 3 * NT], s3 = sv[e + 3 * NT];
                    int p0 = atomicAdd(&g_offset[d0], 1);
                    int p1 = atomicAdd(&g_offset[d1], 1);
                    int p2 = atomicAdd(&g_offset[d2], 1);
                    int p3 = atomicAdd(&g_offset[d3], 1);
                    g_src_sorted[p0] = s0; g_src_sorted[p1] = s1;
                    g_src_sorted[p2] = s2; g_src_sorted[p3] = s3;
                }
                for (; e < N_EDGES; e += NT)
                    g_src_sorted[atomicAdd(&g_offset[dd[e]], 1)] = sv[e];
            }
        }
        __syncthreads();
        // fall through: join the gemm tile pool
    }

    // ========== GEMM: g_Yh = fp16(feat @ W), tf32 3-product mma.sync ======
    const int lane = tid & 31;
    const int wid = tid >> 5;
    const int m0 = (wid >> 1) * 32;       // warp row base (4 groups of 32)
    const int n0 = (wid & 1) * 64;        // warp col base (2 groups of 64)
    const int gID = lane >> 2;            // 0..7
    const int tID = lane & 3;             // 0..3
    const int kq = tid & 7;               // A stage: k-quad
    const int ar0 = tid >> 3;             // A stage: row 0..31
    const int nq = tid & 31;              // B stage: n-quad
    const int kr0 = tid >> 5;             // B stage: k 0..7

    for (;;) {
        __syncthreads();
        if (tid == 0) *(unsigned*)(smem + SM_TILE) = atomicAdd(&g_tile, 1u);
        __syncthreads();
        const unsigned tile = *(const unsigned*)(smem + SM_TILE);
        if (tile >= NGB) break;
        const int row0 = (int)tile * 128;

        float d[2][8][4];
#pragma unroll
        for (int mt = 0; mt < 2; mt++)
#pragma unroll
            for (int nt = 0; nt < 8; nt++)
#pragma unroll
                for (int r = 0; r < 4; r++) d[mt][nt][r] = 0.f;

        for (int c = 0; c < 4; c++) {
            const int k0 = c * 32;
            // ---- stage A: feat[row0..+127][k0..+31] -> {hi,lo} ----
#pragma unroll
            for (int p = 0; p < 4; p++) {
                int r = ar0 + p * 32;
                int row = row0 + r;
                float4 v = make_float4(0.f, 0.f, 0.f, 0.f);
                if (row < N_NODES)
                    v = *(const float4*)(feat + (size_t)row * D + k0 + kq * 4);
                float hx = tf32_hi(v.x), hy = tf32_hi(v.y);
                float hz = tf32_hi(v.z), hw = tf32_hi(v.w);
                float2* dst = smA + r * SA_STRIDE + kq * 4;
                *(float4*)(dst)     = make_float4(hx, tf32_hi(v.x - hx), hy, tf32_hi(v.y - hy));
                *(float4*)(dst + 2) = make_float4(hz, tf32_hi(v.z - hz), hw, tf32_hi(v.w - hw));
            }
            // ---- stage B: W[k0..+31][0..127] -> {hi,lo} ----
#pragma unroll
            for (int p = 0; p < 4; p++) {
                int k = kr0 + p * 8;
                float4 v = *(const float4*)(W + (size_t)(k0 + k) * D + nq * 4);
                float hx = tf32_hi(v.x), hy = tf32_hi(v.y);
                float hz = tf32_hi(v.z), hw = tf32_hi(v.w);
                float2* dst = smB + k * SB_STRIDE + nq * 4;
                *(float4*)(dst)     = make_float4(hx, tf32_hi(v.x - hx), hy, tf32_hi(v.y - hy));
                *(float4*)(dst + 2) = make_float4(hz, tf32_hi(v.z - hz), hw, tf32_hi(v.w - hw));
            }
            __syncthreads();

#pragma unroll
            for (int ks = 0; ks < 4; ks++) {
                const int kb = ks * 8;
                // A fragments (hi in .x, lo in .y)
                float2 aF[2][4];
#pragma unroll
                for (int mt = 0; mt < 2; mt++) {
                    int ma = m0 + mt * 16 + gID;
                    aF[mt][0] = smA[ma * SA_STRIDE + kb + tID];
                    aF[mt][1] = smA[(ma + 8) * SA_STRIDE + kb + tID];
                    aF[mt][2] = smA[ma * SA_STRIDE + kb + tID + 4];
                    aF[mt][3] = smA[(ma + 8) * SA_STRIDE + kb + tID + 4];
                }
#pragma unroll
                for (int nt = 0; nt < 8; nt++) {
                    int nb = n0 + nt * 8 + gID;
                    float2 bA = smB[(kb + tID) * SB_STRIDE + nb];
                    float2 bB = smB[(kb + tID + 4) * SB_STRIDE + nb];
                    uint32_t bh0 = __float_as_uint(bA.x), bh1 = __float_as_uint(bB.x);
                    uint32_t bl0 = __float_as_uint(bA.y), bl1 = __float_as_uint(bB.y);
#pragma unroll
                    for (int mt = 0; mt < 2; mt++) {
                        uint32_t ah0 = __float_as_uint(aF[mt][0].x);
                        uint32_t ah1 = __float_as_uint(aF[mt][1].x);
                        uint32_t ah2 = __float_as_uint(aF[mt][2].x);
                        uint32_t ah3 = __float_as_uint(aF[mt][3].x);
                        uint32_t al0 = __float_as_uint(aF[mt][0].y);
                        uint32_t al1 = __float_as_uint(aF[mt][1].y);
                        uint32_t al2 = __float_as_uint(aF[mt][2].y);
                        uint32_t al3 = __float_as_uint(aF[mt][3].y);
                        MMA_TF32(d[mt][nt], ah0, ah1, ah2, ah3, bh0, bh1);
                        MMA_TF32(d[mt][nt], ah0, ah1, ah2, ah3, bl0, bl1);
                        MMA_TF32(d[mt][nt], al0, al1, al2, al3, bh0, bh1);
                    }
                }
            }
            __syncthreads();
        }

        // ---- epilogue: fp16 stores ----
#pragma unroll
        for (int mt = 0; mt < 2; mt++) {
            int r0 = row0 + m0 + mt * 16 + gID;
            int r1 = r0 + 8;
#pragma unroll
            for (int nt = 0; nt < 8; nt++) {
                int col = n0 + nt * 8 + 2 * tID;
                if (r0 < N_NODES)
                    *(__half2*)(g_Yh + (size_t)r0 * D + col) =
                        __floats2half2_rn(d[mt][nt][0], d[mt][nt][1]);
                if (r1 < N_NODES)
                    *(__half2*)(g_Yh + (size_t)r1 * D + col) =
                        __floats2half2_rn(d[mt][nt][2], d[mt][nt][3]);
            }
        }
    }

    // counter reset for next graph replay
    __syncthreads();
    if (tid == 0) {
        __threadfence();
        unsigned old = atomicAdd(&g_done, 1u);
        if (old == GRID_TOT - 1) { g_tile = 0; g_bar_cnt = 0; g_done = 0; }
    }
}

// ---------------------------------------------------------------------------
// Aggregation: out[n] = sum_{e in seg(n)} Yh[src_sorted[e]] + b.
// fp16 rows halve L2 traffic (164 MB); accumulate in fp32.
// One warp per node; lane covers 4 cols (8B = 2x half2).
// ---------------------------------------------------------------------------
__global__ void __launch_bounds__(256) agg_kernel(const float* __restrict__ bias,
                                                  float* __restrict__ out) {
    int node = (blockIdx.x * blockDim.x + threadIdx.x) >> 5;
    int lane = threadIdx.x & 31;
    if (node >= N_NODES) return;

    const int end = g_offset[node];
    const int beg = end - g_count[node];

    float4 acc = make_float4(0.f, 0.f, 0.f, 0.f);
#pragma unroll 4
    for (int e = beg; e < end; e++) {
        int s = g_src_sorted[e];  // uniform across warp
        uint2 v = ((const uint2*)(g_Yh + (size_t)s * D))[lane];
        __half2 h0 = *(__half2*)&v.x;
        __half2 h1 = *(__half2*)&v.y;
        float2 f0 = __half22float2(h0);
        float2 f1 = __half22float2(h1);
        acc.x += f0.x; acc.y += f0.y; acc.z += f1.x; acc.w += f1.y;
    }

    float4 bv = ((const float4*)bias)[lane];
    ((float4*)(out + (size_t)node * D))[lane] =
        make_float4(acc.x + bv.x, acc.y + bv.y, acc.z + bv.z, acc.w + bv.w);
}

// ---------------------------------------------------------------------------
// Launch: 2 kernels, graph-capturable (no sync, no alloc).
// ---------------------------------------------------------------------------
extern "C" void kernel_launch(void* const* d_in, const int* in_sizes, int n_in,
                              void* d_out, int out_size) {
    const float* feat = (const float*)d_in[0];  // [50000, 128] f32
    const void*  src  = d_in[1];                // [640000] int32/int64
    const void*  dst  = d_in[2];                // [640000] int32/int64
    const float* W    = (const float*)d_in[3];  // [128, 128] f32
    const float* b    = (const float*)d_in[4];  // [1, 128] f32
    float* out = (float*)d_out;                 // [50000, 128] f32

    cudaFuncSetAttribute(mega_kernel, cudaFuncAttributeMaxDynamicSharedMemorySize,
                         SMEM_TOTAL);
    mega_kernel<<<GRID_TOT, 256, SMEM_TOTAL>>>(feat, W, src, dst);
    agg_kernel<<<(N_NODES * 32 + 255) / 256, 256>>>(b, out);
}

// round 11
// speedup vs baseline: 1.2664x; 1.2664x over previous
#include <cuda_runtime.h>
#include <cuda_bf16.h>
#include <cuda_fp16.h>
#include <cstdint>

#define N_NODES 50000
#define D 128
#define N_EDGES 640000
#define S_BLK 64                       // sort blocks (wave-1 resident: < 148)
#define GRID_TOT 296
#define NGB ((N_NODES + 127) / 128)    // 391 gemm tiles
#define CHUNK 4                        // scan items per sort thread
#define NT (S_BLK * 256)               // sort threads = 16384

// Packed fp32x2 FMA (sm_100+): one fma-pipe slot computes two lane-FMAs.
#define FMA2(acc, a, b) \
    asm("fma.rn.f32x2 %0, %1, %2, %0;" : "+l"(acc) : "l"(a), "l"(b))
#define SPLAT2(d, f) \
    asm("mov.b64 %0, {%1, %1};" : "=l"(d) : "f"(f))
#define UNPACK2(lo, hi, v) \
    asm("mov.b64 {%0, %1}, %2;" : "=f"(lo), "=f"(hi) : "l"(v))

// ---- device scratch (no allocs allowed; zero-initialized) ----
__device__ __half g_Yh[(size_t)N_NODES * D];  // feat @ W in fp16 (12.8 MB)
__device__ int   g_count[N_NODES];
__device__ int   g_offset[N_NODES];
__device__ int   g_bsum[S_BLK];
__device__ int   g_bbase[S_BLK];
__device__ int   g_src_sorted[N_EDGES];
__device__ int   g_is64;
__device__ unsigned g_bar_cnt;
__device__ unsigned g_tile;
__device__ unsigned g_done;

__device__ __forceinline__ void sort_barrier(unsigned target) {
    __syncthreads();
    if (threadIdx.x == 0) {
        __threadfence();
        atomicAdd(&g_bar_cnt, 1u);
        while (*((volatile unsigned*)&g_bar_cnt) < target) __nanosleep(64);
        __threadfence();
    }
    __syncthreads();
}

// ---------------------------------------------------------------------------
// Mega kernel: blocks [0,S_BLK) run the sort chain then join the gemm pool;
// the rest run gemm tiles (g_Yh = fp16(feat @ W)) from a stealing counter.
// gemm: 128x128 tile, 8x8 per-thread reg tile held as 8x4 f32x2 pairs,
// Kc=32 staged in smem. NO occupancy clamp (reg cap caused spills before).
// ---------------------------------------------------------------------------
__global__ void __launch_bounds__(256)
mega_kernel(const float* __restrict__ feat, const float* __restrict__ W,
            const void* __restrict__ srcp, const void* __restrict__ dstp) {
    __shared__ float sA[128 * 33];   // A tile, stride-33 padded
    __shared__ float sB[32 * 128];   // B tile [k][col]
    __shared__ int   ss[256];        // sort scan workspace

    const int tid = threadIdx.x;

    if (blockIdx.x < S_BLK) {
        // ================= SORT CHAIN (proven, unchanged) =================
        const int b = blockIdx.x;
        const int st = b * 256 + tid;

        for (int i = st; i < N_NODES; i += NT) g_count[i] = 0;
        if (b == 0 && tid < 32) {
            // int32 read as int64 packs two indices; high half is a random
            // node index (nonzero w.p. ~1-2e-5) -> out-of-range identifies it.
            const long long* s64 = (const long long*)srcp;
            const long long* d64 = (const long long*)dstp;
            int bad = 0;
#pragma unroll
            for (int r = 0; r < 2; r++) {
                int i = tid + r * 32;
                long long a = s64[i], c = d64[i];
                bad |= (a < 0 || a >= N_NODES || c < 0 || c >= N_NODES);
            }
            unsigned m = __ballot_sync(0xFFFFFFFFu, bad);
            if (tid == 0) g_is64 = (m == 0u);
        }
        sort_barrier(1u * S_BLK);

        const int is64 = g_is64;
        {   // hist (4x batched for MLP)
            int e = st;
            if (is64) {
                const long long* dd = (const long long*)dstp;
                for (; e + 3 * NT < N_EDGES; e += 4 * NT) {
                    int d0 = (int)dd[e], d1 = (int)dd[e + NT];
                    int d2 = (int)dd[e + 2 * NT], d3 = (int)dd[e + 3 * NT];
                    atomicAdd(&g_count[d0], 1); atomicAdd(&g_count[d1], 1);
                    atomicAdd(&g_count[d2], 1); atomicAdd(&g_count[d3], 1);
                }
                for (; e < N_EDGES; e += NT) atomicAdd(&g_count[(int)dd[e]], 1);
            } else {
                const int* dd = (const int*)dstp;
                for (; e + 3 * NT < N_EDGES; e += 4 * NT) {
                    int d0 = dd[e], d1 = dd[e + NT];
                    int d2 = dd[e + 2 * NT], d3 = dd[e + 3 * NT];
                    atomicAdd(&g_count[d0], 1); atomicAdd(&g_count[d1], 1);
                    atomicAdd(&g_count[d2], 1); atomicAdd(&g_count[d3], 1);
                }
                for (; e < N_EDGES; e += NT) atomicAdd(&g_count[dd[e]], 1);
            }
        }
        sort_barrier(2u * S_BLK);

        // scan: per-thread sums + block scan
        const int g0 = st * CHUNK;
        int csum = 0, cv[CHUNK];
#pragma unroll
        for (int i = 0; i < CHUNK; i++) {
            int g = g0 + i;
            cv[i] = (g < N_NODES) ? g_count[g] : 0;
            csum += cv[i];
        }
        ss[tid] = csum;
        __syncthreads();
#pragma unroll
        for (int off = 1; off < 256; off <<= 1) {
            int v = ss[tid];
            int u = (tid >= off) ? ss[tid - off] : 0;
            __syncthreads();
            ss[tid] = v + u;
            __syncthreads();
        }
        const int texcl = ss[tid] - csum;
        if (tid == 255) g_bsum[b] = ss[255];
        sort_barrier(3u * S_BLK);

        if (b == 0) {
            int v0 = (tid < S_BLK) ? g_bsum[tid] : 0;
            ss[tid] = v0;
            __syncthreads();
#pragma unroll
            for (int off = 1; off < S_BLK; off <<= 1) {
                int v = ss[tid];
                int u = (tid >= off) ? ss[tid - off] : 0;
                __syncthreads();
                ss[tid] = v + u;
                __syncthreads();
            }
            if (tid < S_BLK) g_bbase[tid] = ss[tid] - v0;
        }
        sort_barrier(4u * S_BLK);

        {
            int run = g_bbase[b] + texcl;
#pragma unroll
            for (int i = 0; i < CHUNK; i++) {
                int g = g0 + i;
                if (g < N_NODES) g_offset[g] = run;
                run += cv[i];
            }
        }
        sort_barrier(5u * S_BLK);

        {   // scatter (4x batched)
            int e = st;
            if (is64) {
                const long long* dd = (const long long*)dstp;
                const long long* sv = (const long long*)srcp;
                for (; e + 3 * NT < N_EDGES; e += 4 * NT) {
                    int d0 = (int)dd[e],          s0 = (int)sv[e];
                    int d1 = (int)dd[e + NT],     s1 = (int)sv[e + NT];
                    int d2 = (int)dd[e + 2 * NT], s2 = (int)sv[e + 2 * NT];
                    int d3 = (int)dd[e + 3 * NT], s3 = (int)sv[e + 3 * NT];
                    int p0 = atomicAdd(&g_offset[d0], 1);
                    int p1 = atomicAdd(&g_offset[d1], 1);
                    int p2 = atomicAdd(&g_offset[d2], 1);
                    int p3 = atomicAdd(&g_offset[d3], 1);
                    g_src_sorted[p0] = s0; g_src_sorted[p1] = s1;
                    g_src_sorted[p2] = s2; g_src_sorted[p3] = s3;
                }
                for (; e < N_EDGES; e += NT)
                    g_src_sorted[atomicAdd(&g_offset[(int)dd[e]], 1)] = (int)sv[e];
            } else {
                const int* dd = (const int*)dstp;
                const int* sv = (const int*)srcp;
                for (; e + 3 * NT < N_EDGES; e += 4 * NT) {
                    int d0 = dd[e],          s0 = sv[e];
                    int d1 = dd[e + NT],     s1 = sv[e + NT];
                    int d2 = dd[e + 2 * NT], s2 = sv[e + 2 * NT];
                    int d3 = dd[e + 3 * NT], s3 = sv[e + 3 * NT];
                    int p0 = atomicAdd(&g_offset[d0], 1);
                    int p1 = atomicAdd(&g_offset[d1], 1);
                    int p2 = atomicAdd(&g_offset[d2], 1);
                    int p3 = atomicAdd(&g_offset[d3], 1);
                    g_src_sorted[p0] = s0; g_src_sorted[p1] = s1;
                    g_src_sorted[p2] = s2; g_src_sorted[p3] = s3;
                }
                for (; e < N_EDGES; e += NT)
                    g_src_sorted[atomicAdd(&g_offset[dd[e]], 1)] = sv[e];
            }
        }
        __syncthreads();
        // fall through: join the gemm tile pool
    }

    // ====== GEMM: g_Yh = fp16(feat @ W), f32x2 FMA, work-stealing ======
    const int tx = tid & 15;          // col group (8 cols = 4 f32x2 pairs)
    const int ty = tid >> 4;          // row group (8 rows)
    const int kq = tid & 7;           // A stage: f4 index in k-chunk
    const int ar0 = tid >> 3;         // A stage: row 0..31
    const int c4 = tid & 31;          // B stage: f4 col
    const int kr0 = tid >> 5;         // B stage: k row 0..7

    __shared__ unsigned s_tile;
    for (;;) {
        __syncthreads();
        if (tid == 0) s_tile = atomicAdd(&g_tile, 1u);
        __syncthreads();
        const unsigned tile = s_tile;
        if (tile >= NGB) break;
        const int row0 = (int)tile * 128;

        unsigned long long acc2[8][4];   // acc2[i][jp] = cols (2jp, 2jp+1)
#pragma unroll
        for (int i = 0; i < 8; i++)
#pragma unroll
            for (int j = 0; j < 4; j++) acc2[i][j] = 0ull;

        for (int k0 = 0; k0 < D; k0 += 32) {
#pragma unroll
            for (int p = 0; p < 4; p++) {
                int r = ar0 + p * 32;
                int row = row0 + r;
                float4 v = make_float4(0.f, 0.f, 0.f, 0.f);
                if (row < N_NODES)
                    v = *(const float4*)(feat + (size_t)row * D + k0 + kq * 4);
                float* dst = &sA[r * 33 + kq * 4];
                dst[0] = v.x; dst[1] = v.y; dst[2] = v.z; dst[3] = v.w;
            }
#pragma unroll
            for (int p = 0; p < 4; p++) {
                int kr = kr0 + p * 8;
                *(float4*)(sB + kr * 128 + c4 * 4) =
                    *(const float4*)(W + (size_t)(k0 + kr) * D + c4 * 4);
            }
            __syncthreads();

#pragma unroll 8
            for (int k = 0; k < 32; k++) {
                // b: 2x LDS.128 reinterpreted as 4 packed f32x2 pairs
                ulonglong2 bl0 = *(const ulonglong2*)(sB + k * 128 + tx * 8);
                ulonglong2 bl1 = *(const ulonglong2*)(sB + k * 128 + tx * 8 + 4);
                unsigned long long b2[4] = {bl0.x, bl0.y, bl1.x, bl1.y};
                unsigned long long a2[8];
#pragma unroll
                for (int i = 0; i < 8; i++) {
                    float av = sA[(ty * 8 + i) * 33 + k];
                    SPLAT2(a2[i], av);
                }
#pragma unroll
                for (int i = 0; i < 8; i++)
#pragma unroll
                    for (int j = 0; j < 4; j++) FMA2(acc2[i][j], a2[i], b2[j]);
            }
            __syncthreads();
        }

        // fp16 epilogue: each acc2 pair -> one half2 store (16B per row seg)
#pragma unroll
        for (int i = 0; i < 8; i++) {
            int row = row0 + ty * 8 + i;
            if (row < N_NODES) {
                __half2 h[4];
#pragma unroll
                for (int j = 0; j < 4; j++) {
                    float lo, hi;
                    UNPACK2(lo, hi, acc2[i][j]);
                    h[j] = __floats2half2_rn(lo, hi);
                }
                *(uint4*)(g_Yh + (size_t)row * D + tx * 8) = *(uint4*)h;
            }
        }
    }

    // counter reset for next graph replay
    __syncthreads();
    if (tid == 0) {
        __threadfence();
        unsigned old = atomicAdd(&g_done, 1u);
        if (old == GRID_TOT - 1) { g_tile = 0; g_bar_cnt = 0; g_done = 0; }
    }
}

// ---------------------------------------------------------------------------
// Aggregation: out[n] = sum_{e in seg(n)} Yh[src_sorted[e]] + b.
// One warp per node; lane covers 4 cols (8B). 2-wide edge unroll doubles
// the independent row loads in flight (loop was latency-bound at issue=45%).
// ---------------------------------------------------------------------------
__global__ void __launch_bounds__(256) agg_kernel(const float* __restrict__ bias,
                                                  float* __restrict__ out) {
    int node = (blockIdx.x * blockDim.x + threadIdx.x) >> 5;
    int lane = threadIdx.x & 31;
    if (node >= N_NODES) return;

    const int end = g_offset[node];
    const int beg = end - g_count[node];

    float4 acc0 = make_float4(0.f, 0.f, 0.f, 0.f);
    float4 acc1 = make_float4(0.f, 0.f, 0.f, 0.f);
    int e = beg;
    for (; e + 1 < end; e += 2) {
        int s0 = g_src_sorted[e];
        int s1 = g_src_sorted[e + 1];
        uint2 v0 = ((const uint2*)(g_Yh + (size_t)s0 * D))[lane];
        uint2 v1 = ((const uint2*)(g_Yh + (size_t)s1 * D))[lane];
        float2 a = __half22float2(*(__half2*)&v0.x);
        float2 b = __half22float2(*(__half2*)&v0.y);
        float2 c = __half22float2(*(__half2*)&v1.x);
        float2 d = __half22float2(*(__half2*)&v1.y);
        acc0.x += a.x; acc0.y += a.y; acc0.z += b.x; acc0.w += b.y;
        acc1.x += c.x; acc1.y += c.y; acc1.z += d.x; acc1.w += d.y;
    }
    if (e < end) {
        int s = g_src_sorted[e];
        uint2 v = ((const uint2*)(g_Yh + (size_t)s * D))[lane];
        float2 a = __half22float2(*(__half2*)&v.x);
        float2 b = __half22float2(*(__half2*)&v.y);
        acc0.x += a.x; acc0.y += a.y; acc0.z += b.x; acc0.w += b.y;
    }

    float4 bv = ((const float4*)bias)[lane];
    ((float4*)(out + (size_t)node * D))[lane] = make_float4(
        acc0.x + acc1.x + bv.x, acc0.y + acc1.y + bv.y,
        acc0.z + acc1.z + bv.z, acc0.w + acc1.w + bv.w);
}

// ---------------------------------------------------------------------------
// Launch: 2 kernels, graph-capturable (no sync, no alloc).
// ---------------------------------------------------------------------------
extern "C" void kernel_launch(void* const* d_in, const int* in_sizes, int n_in,
                              void* d_out, int out_size) {
    const float* feat = (const float*)d_in[0];  // [50000, 128] f32
    const void*  src  = d_in[1];                // [640000] int32/int64
    const void*  dst  = d_in[2];                // [640000] int32/int64
    const float* W    = (const float*)d_in[3];  // [128, 128] f32
    const float* b    = (const float*)d_in[4];  // [1, 128] f32
    float* out = (float*)d_out;                 // [50000, 128] f32

    mega_kernel<<<GRID_TOT, 256>>>(feat, W, src, dst);
    agg_kernel<<<(N_NODES * 32 + 255) / 256, 256>>>(b, out);
}